// round 1
// baseline (speedup 1.0000x reference)
#include <cuda_runtime.h>

#define NE   1024
#define NIN  64
#define HID  128
#define NOUT 64
#define TI   4   // rows of i per block in the pairwise kernel

// Scratch (allocation-free rule: __device__ globals)
__device__ float g_A[NE * HID];  // x @ W1[:64]  + b1
__device__ float g_B[NE * HID];  // x @ W1[64:]

__device__ __forceinline__ float tanh_fast(float x) {
    float y;
    asm("tanh.approx.f32 %0, %1;" : "=f"(y) : "f"(x));
    return y;
}

// ---------------------------------------------------------------------------
// K1: projection. A[i,h] = sum_f x[i,f] * W1[f,h] + b1[h]
//                 B[i,h] = sum_f x[i,f] * W1[64+f,h]
// grid = NE blocks, HID threads
// ---------------------------------------------------------------------------
__global__ void k_proj(const float* __restrict__ x,
                       const float* __restrict__ W1,
                       const float* __restrict__ b1) {
    const int i = blockIdx.x;
    const int h = threadIdx.x;  // 0..127

    __shared__ float sx[NIN];
    if (h < NIN) sx[h] = x[i * NIN + h];
    __syncthreads();

    float a = b1[h];
    float b = 0.0f;
#pragma unroll
    for (int f = 0; f < NIN; f++) {
        const float xf = sx[f];
        a = fmaf(xf, W1[f * HID + h], a);
        b = fmaf(xf, W1[(NIN + f) * HID + h], b);
    }
    g_A[i * HID + h] = a;
    g_B[i * HID + h] = b;
}

// ---------------------------------------------------------------------------
// K2: pairwise tanh reduction + fused output GEMM.
// Block b handles rows r0 = b*TI .. b*TI+TI-1. Thread = hidden unit h.
// acc[r,h] = (sum_{p != r} tanh(A[r,h] + B[p,h])) / 1023
// out[r,:] = acc[r,:] @ W2 + b2
// grid = NE/TI = 256 blocks, HID = 128 threads
// ---------------------------------------------------------------------------
__global__ void k_pair(const float* __restrict__ W2,
                       const float* __restrict__ b2,
                       float* __restrict__ out) {
    const int h  = threadIdx.x;      // 0..127
    const int r0 = blockIdx.x * TI;

    const float a0 = g_A[(r0 + 0) * HID + h];
    const float a1 = g_A[(r0 + 1) * HID + h];
    const float a2 = g_A[(r0 + 2) * HID + h];
    const float a3 = g_A[(r0 + 3) * HID + h];

    float s0 = 0.f, s1 = 0.f, s2 = 0.f, s3 = 0.f;

    const float* __restrict__ gB = g_B;
#pragma unroll 8
    for (int p = 0; p < NE; p++) {
        const float bv = __ldg(&gB[p * HID + h]);
        s0 += tanh_fast(a0 + bv);
        s1 += tanh_fast(a1 + bv);
        s2 += tanh_fast(a2 + bv);
        s3 += tanh_fast(a3 + bv);
    }

    // remove self terms (p == i excluded by the reference's partner index)
    s0 -= tanh_fast(a0 + gB[(r0 + 0) * HID + h]);
    s1 -= tanh_fast(a1 + gB[(r0 + 1) * HID + h]);
    s2 -= tanh_fast(a2 + gB[(r0 + 2) * HID + h]);
    s3 -= tanh_fast(a3 + gB[(r0 + 3) * HID + h]);

    const float inv = 1.0f / (float)(NE - 1);

    __shared__ float sacc[TI][HID];
    sacc[0][h] = s0 * inv;
    sacc[1][h] = s1 * inv;
    sacc[2][h] = s2 * inv;
    sacc[3][h] = s3 * inv;
    __syncthreads();

    // Epilogue: TI*NOUT = 256 outputs, 128 threads -> 2 outputs each.
    // Warp-uniform row r per iteration => sacc reads are smem broadcasts,
    // W2 reads are coalesced across o.
#pragma unroll
    for (int k = 0; k < (TI * NOUT) / HID; k++) {
        const int idx = k * HID + h;       // 0..255
        const int r   = idx >> 6;          // /NOUT
        const int o   = idx & (NOUT - 1);
        float acc = b2[o];
#pragma unroll
        for (int hh = 0; hh < HID; hh++)
            acc = fmaf(sacc[r][hh], W2[hh * NOUT + o], acc);
        out[(r0 + r) * NOUT + o] = acc;
    }
}

// ---------------------------------------------------------------------------
extern "C" void kernel_launch(void* const* d_in, const int* in_sizes, int n_in,
                              void* d_out, int out_size) {
    const float* x  = (const float*)d_in[0];
    const float* W1 = (const float*)d_in[1];
    const float* b1 = (const float*)d_in[2];
    const float* W2 = (const float*)d_in[3];
    const float* b2 = (const float*)d_in[4];
    float* out = (float*)d_out;

    k_proj<<<NE, HID>>>(x, W1, b1);
    k_pair<<<NE / TI, HID>>>(W2, b2, out);
}

// round 2
// speedup vs baseline: 2.1369x; 2.1369x over previous
#include <cuda_runtime.h>

#define NE     1024
#define NIN    64
#define HID    128
#define NOUT   64
#define TI     4          // rows of i per block
#define PSPLIT 4          // partner-range split (parallelism without extra L2 traffic)
#define PCHUNK (NE / PSPLIT)   // 256 partners per block

// Scratch (allocation-free rule: __device__ globals)
__device__ float g_A[NE * HID];           // x @ W1[:64] + b1
__device__ float g_B[NE * HID];           // x @ W1[64:]
__device__ float g_P[PSPLIT][NE * HID];   // partial tanh-sums

__device__ __forceinline__ float tanh_fast(float x) {
    float y;
    asm("tanh.approx.f32 %0, %1;" : "=f"(y) : "f"(x));
    return y;
}

// ---------------------------------------------------------------------------
// K1: projection. A[i,h] = sum_f x[i,f]*W1[f,h] + b1[h]; B[i,h] = sum_f x[i,f]*W1[64+f,h]
// grid = NE, block = HID
// ---------------------------------------------------------------------------
__global__ void k_proj(const float* __restrict__ x,
                       const float* __restrict__ W1,
                       const float* __restrict__ b1) {
    const int i = blockIdx.x;
    const int h = threadIdx.x;

    __shared__ float sx[NIN];
    if (h < NIN) sx[h] = x[i * NIN + h];
    __syncthreads();

    float a = b1[h];
    float b = 0.0f;
#pragma unroll
    for (int f = 0; f < NIN; f++) {
        const float xf = sx[f];
        a = fmaf(xf, W1[f * HID + h], a);
        b = fmaf(xf, W1[(NIN + f) * HID + h], b);
    }
    g_A[i * HID + h] = a;
    g_B[i * HID + h] = b;
}

// ---------------------------------------------------------------------------
// K2: pairwise tanh partial sums.
// Block (bx, ps): rows r0 = bx*TI .. +3, partners [ps*PCHUNK, (ps+1)*PCHUNK).
// grid = (NE/TI, PSPLIT) = (256, 4) -> 1024 blocks, 128 threads.
// Self-term subtraction deferred to the combine kernel.
// ---------------------------------------------------------------------------
__global__ void __launch_bounds__(128, 8)
k_pair(void) {
    const int h  = threadIdx.x;           // hidden unit
    const int r0 = blockIdx.x * TI;
    const int ps = blockIdx.y;

    const float a0 = g_A[(r0 + 0) * HID + h];
    const float a1 = g_A[(r0 + 1) * HID + h];
    const float a2 = g_A[(r0 + 2) * HID + h];
    const float a3 = g_A[(r0 + 3) * HID + h];

    float s0 = 0.f, s1 = 0.f, s2 = 0.f, s3 = 0.f;

    const float* __restrict__ gB = g_B + ps * PCHUNK * HID + h;
#pragma unroll 8
    for (int p = 0; p < PCHUNK; p++) {
        const float bv = __ldg(&gB[p * HID]);
        s0 += tanh_fast(a0 + bv);
        s1 += tanh_fast(a1 + bv);
        s2 += tanh_fast(a2 + bv);
        s3 += tanh_fast(a3 + bv);
    }

    float* __restrict__ gP = g_P[ps];
    gP[(r0 + 0) * HID + h] = s0;
    gP[(r0 + 1) * HID + h] = s1;
    gP[(r0 + 2) * HID + h] = s2;
    gP[(r0 + 3) * HID + h] = s3;
}

// ---------------------------------------------------------------------------
// K3: combine partials, subtract self term, scale, fused W2 epilogue.
// grid = NE/TI = 256 blocks, 128 threads.
// ---------------------------------------------------------------------------
__global__ void k_combine(const float* __restrict__ W2,
                          const float* __restrict__ b2,
                          float* __restrict__ out) {
    const int h  = threadIdx.x;
    const int r0 = blockIdx.x * TI;
    const float inv = 1.0f / (float)(NE - 1);

    __shared__ float sacc[TI][HID];
#pragma unroll
    for (int r = 0; r < TI; r++) {
        const int idx = (r0 + r) * HID + h;
        float s = g_P[0][idx] + g_P[1][idx] + g_P[2][idx] + g_P[3][idx];
        s -= tanh_fast(g_A[idx] + g_B[idx]);   // exclude p == i
        sacc[r][h] = s * inv;
    }
    __syncthreads();

    // TI*NOUT = 256 outputs, 128 threads -> 2 each. Warp-uniform row r per
    // iteration: sacc reads broadcast, W2 reads coalesced across o.
#pragma unroll
    for (int k = 0; k < (TI * NOUT) / HID; k++) {
        const int idx = k * HID + h;
        const int r   = idx >> 6;            // / NOUT
        const int o   = idx & (NOUT - 1);
        float acc = b2[o];
#pragma unroll
        for (int hh = 0; hh < HID; hh++)
            acc = fmaf(sacc[r][hh], W2[hh * NOUT + o], acc);
        out[(r0 + r) * NOUT + o] = acc;
    }
}

// ---------------------------------------------------------------------------
extern "C" void kernel_launch(void* const* d_in, const int* in_sizes, int n_in,
                              void* d_out, int out_size) {
    const float* x  = (const float*)d_in[0];
    const float* W1 = (const float*)d_in[1];
    const float* b1 = (const float*)d_in[2];
    const float* W2 = (const float*)d_in[3];
    const float* b2 = (const float*)d_in[4];
    float* out = (float*)d_out;

    k_proj<<<NE, HID>>>(x, W1, b1);
    dim3 grid2(NE / TI, PSPLIT);
    k_pair<<<grid2, HID>>>();
    k_combine<<<NE / TI, HID>>>(W2, b2, out);
}